// round 16
// baseline (speedup 1.0000x reference)
#include <cuda_runtime.h>
#include <cstdint>

#define L 1024
#define D 64
#define NBH 64
#define OUT_ELEMS (NBH*L*D)
#define SQ 68    // padded row stride for Q/K tiles (floats)
#define PS 132   // padded row stride for e tile (floats)

__device__ __forceinline__ uint32_t f2tf(float x) {
    uint32_t r; asm("cvt.rna.tf32.f32 %0, %1;" : "=r"(r) : "f"(x)); return r;
}

__device__ __forceinline__ void mma_tf32(float* c,
    uint32_t a0, uint32_t a1, uint32_t a2, uint32_t a3, uint32_t b0, uint32_t b1)
{
    asm("mma.sync.aligned.m16n8k8.row.col.f32.tf32.tf32.f32 "
        "{%0,%1,%2,%3}, {%4,%5,%6,%7}, {%8,%9}, {%0,%1,%2,%3};"
        : "+f"(c[0]), "+f"(c[1]), "+f"(c[2]), "+f"(c[3])
        : "r"(a0), "r"(a1), "r"(a2), "r"(a3), "r"(b0), "r"(b1));
}

// ---------------------------------------------------------------------------
// Fused attention: per CTA a 64-row strip of one (b,h).
// Per kt (128 K rows): S=QK^T (3xTF32 mma) -> mask/bias/exp -> e to gmem +
// e to smem Ps -> PV mma accumulates O_unnorm over the strip. At strip end:
// l known -> out = O_unnorm/l written, and this CTA re-scales its own e->p
// in gmem (e still L2-hot). No inter-kernel DRAM round-trip of e for MMA.
// Warps: wq=wid&3 (16 rows), wk=wid>>2 (64 of 128 kt cols).  acc_s 32 +
// acc_o 32 regs. Ps regions are same-warp between QK-epilogue and PV.
// ---------------------------------------------------------------------------
__global__ __launch_bounds__(256, 2)
void fused_kernel(const float* __restrict__ Q, const float* __restrict__ K,
                  const float* __restrict__ V,
                  const int* __restrict__ mask, const float* __restrict__ bias,
                  float* __restrict__ score, float* __restrict__ out)
{
    extern __shared__ float sm[];
    float* Qs   = sm;                    // 64 x 68   = 4352
    float* Ks   = sm + 4352;             // 128 x 68  = 8704 (aliased by VF)
    float* Ps   = sm + 4352 + 8704;      // 64 x 132  = 8448
    float* sred = Ps + 8448;             // 128
    float* sinv = sred + 128;            // 64
    uint32_t* VF = (uint32_t*)Ks;        // 8192 uints: V fragments (tf32)

    const int tid  = threadIdx.x;
    const int lane = tid & 31, wid = tid >> 5;
    const int wq = wid & 3, wk = wid >> 2;
    const int g = lane >> 2, t = lane & 3;
    const int qt = blockIdx.x, bh = blockIdx.y;
    const int b = bh >> 4, h = bh & 15;

    // Q tile (64 rows), raw padded
    {
        const float4* Qg = (const float4*)(Q + ((size_t)bh * L + qt * 64) * D);
        #pragma unroll
        for (int it = 0; it < 4; it++) {
            int i = tid + it * 256; int r = i >> 4, dq = i & 15;
            ((float4*)(Qs + r * SQ))[dq] = Qg[r * 16 + dq];
        }
    }

    const float4* Vg = (const float4*)(V + (size_t)bh * L * D);

    float l_run[2] = {0.f, 0.f};
    float acc_o[8][4];                 // 16 rows x 64 d, partial over k half wk
    #pragma unroll
    for (int nt = 0; nt < 8; nt++)
        #pragma unroll
        for (int r = 0; r < 4; r++) acc_o[nt][r] = 0.f;

    // V-scatter constants (128 rows/tile, 2 threads per row)
    const int vrow = tid >> 1;                    // 0..127 (k within tile)
    const int vkk = vrow >> 3, vts = vrow & 7;
    const int vword = vts >> 2, vt = vts & 3;

    for (int kt = 0; kt < 8; kt++) {
        __syncthreads();                          // prev PV done with VF(=Ks)
        {   // K tile 128 x 64
            const float4* Kg = (const float4*)(K + ((size_t)bh * L + kt * 128) * D);
            #pragma unroll
            for (int it = 0; it < 8; it++) {
                int i = tid + it * 256; int r = i >> 4, dq = i & 15;
                ((float4*)(Ks + r * SQ))[dq] = Kg[r * 16 + dq];
            }
        }
        __syncthreads();

        // ---- QK MMA ----
        float acc_s[8][4];
        #pragma unroll
        for (int nt = 0; nt < 8; nt++)
            #pragma unroll
            for (int r = 0; r < 4; r++) acc_s[nt][r] = 0.f;

        const float* Qw = Qs + (wq * 16) * SQ;
        const float* Kw = Ks + (wk * 64) * SQ;

        #pragma unroll
        for (int kk = 0; kk < 8; kk++) {
            uint32_t ahi[4], alo[4];
            #pragma unroll
            for (int r = 0; r < 4; r++) {
                int row = g + (r & 1) * 8;
                int col = kk * 8 + t + (r >> 1) * 4;
                float x = Qw[row * SQ + col];
                uint32_t hi = f2tf(x);
                ahi[r] = hi;
                alo[r] = f2tf(x - __uint_as_float(hi));
            }
            #pragma unroll
            for (int nt = 0; nt < 8; nt++) {
                uint32_t bhi[2], blo[2];
                #pragma unroll
                for (int r = 0; r < 2; r++) {
                    float x = Kw[(nt * 8 + g) * SQ + kk * 8 + t + r * 4];
                    uint32_t hi = f2tf(x);
                    bhi[r] = hi;
                    blo[r] = f2tf(x - __uint_as_float(hi));
                }
                mma_tf32(acc_s[nt], ahi[0], ahi[1], ahi[2], ahi[3], blo[0], blo[1]);
                mma_tf32(acc_s[nt], alo[0], alo[1], alo[2], alo[3], bhi[0], bhi[1]);
                mma_tf32(acc_s[nt], ahi[0], ahi[1], ahi[2], ahi[3], bhi[0], bhi[1]);
            }
        }

        // ---- epilogue: mask/bias/exp -> e to gmem + Ps; accumulate l ----
        const int cp0 = kt * 64 + wk * 32;        // float2 col base (global)
        #pragma unroll
        for (int hf = 0; hf < 2; hf++) {
            int rowl = wq * 16 + hf * 8 + g;
            int rowg = qt * 64 + rowl;
            const int2*   mrow = (const int2*)  (mask  + ((size_t)b  * L + rowg) * L);
            const float2* brow = (const float2*)(bias  + ((size_t)h  * L + rowg) * L);
            float2*       srow = (float2*)      (score + ((size_t)bh * L + rowg) * L);
            float2*       prow = (float2*)(Ps + rowl * PS);
            float lsum = 0.f;
            #pragma unroll
            for (int nt = 0; nt < 8; nt++) {
                int cp = cp0 + nt * 4 + t;
                int2   mv = mrow[cp];
                float2 bv = brow[cp];
                float s0 = acc_s[nt][hf * 2 + 0] * 0.125f;
                float s1 = acc_s[nt][hf * 2 + 1] * 0.125f;
                s0 = (mv.x == 0 ? -10000.f : s0) + bv.x;
                s1 = (mv.y == 0 ? -10000.f : s1) + bv.y;
                float e0 = __expf(s0), e1 = __expf(s1);
                srow[cp] = make_float2(e0, e1);
                prow[wk * 32 + nt * 4 + t] = make_float2(e0, e1);
                lsum += e0 + e1;
            }
            l_run[hf] += lsum;
        }
        __syncthreads();                          // all QK reads of Ks done

        // ---- V tile -> VF fragments (overwrites Ks) ----
        #pragma unroll
        for (int it = 0; it < 8; it++) {
            int qd = (tid & 1) + it * 2;          // float4 col 0..15
            float4 sv = Vg[(size_t)(kt * 128 + vrow) * 16 + qd];
            #pragma unroll
            for (int j = 0; j < 4; j++) {
                int n = qd * 4 + j;
                int nt = n >> 3, gn = n & 7;
                VF[((vkk * 8 + nt) * 32 + gn * 4 + vt) * 2 + vword] = f2tf((&sv.x)[j]);
            }
        }
        __syncthreads();                          // VF ready

        // ---- PV MMA: acc_o += P(16 x 64, own half) x V(64 x 64) ----
        const uint2* VF2 = (const uint2*)VF;
        #pragma unroll
        for (int kk2 = 0; kk2 < 8; kk2++) {
            uint32_t a[4];
            #pragma unroll
            for (int w = 0; w < 4; w++) {
                float x = Ps[(wq * 16 + g + 8 * (w & 1)) * PS
                             + wk * 64 + kk2 * 8 + t + 4 * (w >> 1)];
                a[w] = f2tf(x);
            }
            int kkg = wk * 8 + kk2;
            #pragma unroll
            for (int nt = 0; nt < 8; nt++) {
                uint2 bb = VF2[(kkg * 8 + nt) * 32 + lane];
                mma_tf32(acc_o[nt], a[0], a[1], a[2], a[3], bb.x, bb.y);
            }
        }
    }

    // ---- l reduction -> sinv ----
    #pragma unroll
    for (int li = 0; li < 2; li++) {
        l_run[li] += __shfl_xor_sync(0xffffffffu, l_run[li], 1);
        l_run[li] += __shfl_xor_sync(0xffffffffu, l_run[li], 2);
    }
    // wk==0 warps park their partial O in Ps scratch (own-warp region)
    if (wk == 0) {
        #pragma unroll
        for (int hf = 0; hf < 2; hf++) {
            float2* pr = (float2*)(Ps + (wq * 16 + hf * 8 + g) * PS);
            #pragma unroll
            for (int nt = 0; nt < 8; nt++)
                pr[nt * 4 + t] = make_float2(acc_o[nt][hf * 2], acc_o[nt][hf * 2 + 1]);
        }
    }
    if (t == 0) {
        #pragma unroll
        for (int li = 0; li < 2; li++)
            sred[wk * 64 + wq * 16 + li * 8 + g] = l_run[li];
    }
    __syncthreads();
    if (tid < 64) sinv[tid] = 1.0f / (sred[tid] + sred[64 + tid]);
    __syncthreads();

    // ---- wk==1 warps: combine halves, normalize, write out ----
    if (wk == 1) {
        #pragma unroll
        for (int hf = 0; hf < 2; hf++) {
            int rowl = wq * 16 + hf * 8 + g;
            float il = sinv[rowl];
            const float2* pr = (const float2*)(Ps + rowl * PS);
            float2* orow = (float2*)(out + ((size_t)bh * L + qt * 64 + rowl) * D);
            #pragma unroll
            for (int nt = 0; nt < 8; nt++) {
                float2 part = pr[nt * 4 + t];
                orow[nt * 4 + t] = make_float2(
                    (part.x + acc_o[nt][hf * 2])     * il,
                    (part.y + acc_o[nt][hf * 2 + 1]) * il);
            }
        }
    }

    // ---- scale own e -> p in gmem (L2-hot read, DRAM write) ----
    float* sst = score + ((size_t)bh * L + qt * 64) * L;
    #pragma unroll 4
    for (int it = 0; it < 64; it++) {
        int idx = tid + it * 256;                 // float4 index, 16384 total
        int r = idx >> 8, c = idx & 255;
        float4* rp = (float4*)(sst + (size_t)r * L);
        float4 v = rp[c];
        float il = sinv[r];
        v.x *= il; v.y *= il; v.z *= il; v.w *= il;
        rp[c] = v;
    }
}

// ---------------------------------------------------------------------------
extern "C" void kernel_launch(void* const* d_in, const int* in_sizes, int n_in,
                              void* d_out, int out_size)
{
    const float* Q    = (const float*)d_in[0];
    const float* K    = (const float*)d_in[1];
    const float* V    = (const float*)d_in[2];
    const int*   mask = (const int*)  d_in[3];
    const float* bias = (const float*)d_in[4];

    float* out   = (float*)d_out;
    float* score = out + OUT_ELEMS;   // tuple order: (out, score)

    const int smem = (4352 + 8704 + 8448 + 128 + 64) * 4;   // 86784 B
    cudaFuncSetAttribute(fused_kernel, cudaFuncAttributeMaxDynamicSharedMemorySize, smem);

    fused_kernel<<<dim3(16, 64), 256, smem>>>(Q, K, V, mask, bias, score, out);
}

// round 17
// speedup vs baseline: 1.5850x; 1.5850x over previous
#include <cuda_runtime.h>
#include <cstdint>

#define L 1024
#define D 64
#define NBH 64
#define OUT_ELEMS (NBH*L*D)
#define SQ 68   // padded row stride (floats) for Q/K smem

__device__ float g_inv_l[NBH * L];   // per-row 1/sum(exp(s)), qk -> pv

__device__ __forceinline__ uint32_t f2tf(float x) {
    uint32_t r; asm("cvt.rna.tf32.f32 %0, %1;" : "=r"(r) : "f"(x)); return r;
}

__device__ __forceinline__ void mma_tf32(float* c,
    uint32_t a0, uint32_t a1, uint32_t a2, uint32_t a3, uint32_t b0, uint32_t b1)
{
    asm("mma.sync.aligned.m16n8k8.row.col.f32.tf32.tf32.f32 "
        "{%0,%1,%2,%3}, {%4,%5,%6,%7}, {%8,%9}, {%0,%1,%2,%3};"
        : "+f"(c[0]), "+f"(c[1]), "+f"(c[2]), "+f"(c[3])
        : "r"(a0), "r"(a1), "r"(a2), "r"(a3), "r"(b0), "r"(b1));
}

// ---------------------------------------------------------------------------
// Kernel 1 (R13 structure; 2-term TF32 split: a*b ~= (ahi+alo)*bhi).
// Per (qt, bh) strip of 128 x 1024:
// e = exp(QK^T/8 masked + bias) -> score buffer (holds exp!), and
// g_inv_l = 1 / row-sum(e).  Raw padded-row smem, in-loop hi/lo split of A,
// B uses hi only (dropped ahi*blo term: ~3.4e-4 extra rel err, within budget).
// Smem 70656 B -> 2 CTAs/SM + 86 KB L1.
// ---------------------------------------------------------------------------
__global__ __launch_bounds__(256, 2)
void qks_kernel(const float* __restrict__ Q, const float* __restrict__ K,
                const int* __restrict__ mask, const float* __restrict__ bias,
                float* __restrict__ score)
{
    extern __shared__ float sm[];
    float* Qs   = sm;                 // 128 x 68
    float* Ks   = sm + 128 * SQ;      // 128 x 68
    float* sred = sm + 2 * 128 * SQ;  // 2 x 128

    const int tid  = threadIdx.x;
    const int lane = tid & 31, wid = tid >> 5;
    const int wq = wid & 3, wk = wid >> 2;
    const int g = lane >> 2, t = lane & 3;
    const int qt = blockIdx.x, bh = blockIdx.y;
    const int b = bh >> 4, h = bh & 15;

    // load Q tile (stays for whole strip)
    {
        const float4* Qg = (const float4*)(Q + ((size_t)bh * L + qt * 128) * D);
        #pragma unroll
        for (int it = 0; it < 8; it++) {
            int i = tid + it * 256; int r = i >> 4, dq = i & 15;
            ((float4*)(Qs + r * SQ))[dq] = Qg[r * 16 + dq];
        }
    }

    float l_run[4] = {0.f, 0.f, 0.f, 0.f};

    for (int kt = 0; kt < 8; kt++) {
        __syncthreads();
        {
            const float4* Kg = (const float4*)(K + ((size_t)bh * L + kt * 128) * D);
            #pragma unroll
            for (int it = 0; it < 8; it++) {
                int i = tid + it * 256; int r = i >> 4, dq = i & 15;
                ((float4*)(Ks + r * SQ))[dq] = Kg[r * 16 + dq];
            }
        }
        __syncthreads();

        float acc[2][8][4];
        #pragma unroll
        for (int mt = 0; mt < 2; mt++)
            #pragma unroll
            for (int nt = 0; nt < 8; nt++)
                #pragma unroll
                for (int r = 0; r < 4; r++) acc[mt][nt][r] = 0.f;

        const float* Qw = Qs + (wq * 32) * SQ;
        const float* Kw = Ks + (wk * 64) * SQ;

        #pragma unroll
        for (int kk = 0; kk < 8; kk++) {
            uint32_t ahi[2][4], alo[2][4];
            #pragma unroll
            for (int mt = 0; mt < 2; mt++)
                #pragma unroll
                for (int r = 0; r < 4; r++) {
                    int row = mt * 16 + g + (r & 1) * 8;
                    int col = kk * 8 + t + (r >> 1) * 4;
                    float x = Qw[row * SQ + col];
                    uint32_t hi = f2tf(x);
                    ahi[mt][r] = hi;
                    alo[mt][r] = f2tf(x - __uint_as_float(hi));
                }
            #pragma unroll
            for (int nt = 0; nt < 8; nt++) {
                uint32_t bhi[2];
                bhi[0] = f2tf(Kw[(nt * 8 + g) * SQ + kk * 8 + t]);
                bhi[1] = f2tf(Kw[(nt * 8 + g) * SQ + kk * 8 + t + 4]);
                #pragma unroll
                for (int mt = 0; mt < 2; mt++) {
                    mma_tf32(acc[mt][nt], alo[mt][0], alo[mt][1], alo[mt][2], alo[mt][3], bhi[0], bhi[1]);
                    mma_tf32(acc[mt][nt], ahi[mt][0], ahi[mt][1], ahi[mt][2], ahi[mt][3], bhi[0], bhi[1]);
                }
            }
        }

        // epilogue: scale, mask, bias, store e=exp(s), accumulate l
        const int q0 = qt * 128 + wq * 32;
        const int cp0 = kt * 64 + wk * 32;   // float2 col-index base
        #pragma unroll
        for (int mt = 0; mt < 2; mt++)
            #pragma unroll
            for (int half = 0; half < 2; half++) {
                int row = q0 + mt * 16 + half * 8 + g;
                const int2*   mrow = (const int2*)  (mask  + ((size_t)b  * L + row) * L);
                const float2* brow = (const float2*)(bias  + ((size_t)h  * L + row) * L);
                float2*       srow = (float2*)      (score + ((size_t)bh * L + row) * L);
                float lsum = 0.f;
                #pragma unroll
                for (int nt = 0; nt < 8; nt++) {
                    int cp = cp0 + nt * 4 + t;
                    int2   mv = mrow[cp];
                    float2 bv = brow[cp];
                    float s0 = acc[mt][nt][half * 2 + 0] * 0.125f;
                    float s1 = acc[mt][nt][half * 2 + 1] * 0.125f;
                    s0 = (mv.x == 0 ? -10000.f : s0) + bv.x;
                    s1 = (mv.y == 0 ? -10000.f : s1) + bv.y;
                    float e0 = __expf(s0), e1 = __expf(s1);
                    srow[cp] = make_float2(e0, e1);
                    lsum += e0 + e1;
                }
                l_run[mt * 2 + half] += lsum;
            }
    }

    #pragma unroll
    for (int li = 0; li < 4; li++) {
        l_run[li] += __shfl_xor_sync(0xffffffffu, l_run[li], 1);
        l_run[li] += __shfl_xor_sync(0xffffffffu, l_run[li], 2);
    }
    __syncthreads();
    if (t == 0) {
        #pragma unroll
        for (int li = 0; li < 4; li++) {
            int row = wq * 32 + (li >> 1) * 16 + (li & 1) * 8 + g;
            sred[wk * 128 + row] = l_run[li];
        }
    }
    __syncthreads();
    if (tid < 128) {
        float l = sred[tid] + sred[128 + tid];
        g_inv_l[(size_t)bh * L + qt * 128 + tid] = 1.0f / l;
    }
}

// ---------------------------------------------------------------------------
// Kernel 2 (R13 pv verbatim, 194.9us measured): O = P V with P = e * inv_l;
// writes normalized p over e in score. Fragment-major pre-converted tf32 smem;
// double-buffered, 1 sync/chunk; register-staged pipeline.
// ---------------------------------------------------------------------------
#define PVBUF 12288   // uints per buffer: AF 8192 + VF 4096

struct Stage { float4 se[8]; float4 sv[4]; };

__device__ __forceinline__ void load_stage(Stage& st, const float* sbase,
                                           const float4* Vg, int c, int tid)
{
    const int prow = tid >> 1;
    #pragma unroll
    for (int it = 0; it < 8; it++) {
        int qcol = (tid & 1) + it * 2;
        st.se[it] = *(const float4*)(sbase + (size_t)prow * L + c * 64 + qcol * 4);
    }
    const int vrow = tid >> 2;
    #pragma unroll
    for (int it = 0; it < 4; it++) {
        int qd = (tid & 3) + it * 4;
        st.sv[it] = Vg[(size_t)(c * 64 + vrow) * 16 + qd];
    }
}

__global__ __launch_bounds__(256, 2)
void pv_kernel(const float* __restrict__ V, float* score, float* __restrict__ out)
{
    extern __shared__ uint32_t smu[];
    // two buffers of {AF[8192], VF[4096]}, then sinv
    float* sinv = (float*)(smu + 2 * PVBUF);   // 128 floats

    const int tid  = threadIdx.x;
    const int lane = tid & 31, wid = tid >> 5;
    const int g = lane >> 2, t = lane & 3;
    const int qt = blockIdx.x, bh = blockIdx.y;

    const float4* Vg    = (const float4*)(V + (size_t)bh * L * D);
    float*        sbase = score + ((size_t)bh * L + qt * 128) * L;

    Stage st;
    load_stage(st, sbase, Vg, 0, tid);
    if (tid < 128) sinv[tid] = g_inv_l[(size_t)bh * L + qt * 128 + tid];
    __syncthreads();
    const float il = sinv[tid >> 1];

    float acc[8][4];
    #pragma unroll
    for (int nt = 0; nt < 8; nt++)
        #pragma unroll
        for (int r = 0; r < 4; r++) acc[nt][r] = 0.f;

    // per-thread constant scatter indices
    const int prow = tid >> 1;
    const int wqr = prow >> 4, gp = prow & 15, gg = gp & 7, rlo = gp >> 3;
    const int vrow = tid >> 2;
    const int vkk = vrow >> 3, ts = vrow & 7, vword = ts >> 2, vt = ts & 3;

    for (int c = 0; c < 16; c++) {
        uint32_t* AF = smu + (c & 1) * PVBUF;
        uint32_t* VF = AF + 8192;

        // ---- transform + store stage: p = e*il -> gmem + fragment smem ----
        #pragma unroll
        for (int it = 0; it < 8; it++) {
            int qcol = (tid & 1) + it * 2;
            float4 p;
            p.x = st.se[it].x * il; p.y = st.se[it].y * il;
            p.z = st.se[it].z * il; p.w = st.se[it].w * il;
            *(float4*)(sbase + (size_t)prow * L + c * 64 + qcol * 4) = p;
            int kk = qcol >> 1, r = ((qcol & 1) << 1) | rlo;
            uint32_t* dst = AF + (wqr * 8 + kk) * 128 + r;
            dst[(gg * 4 + 0) * 4] = f2tf(p.x);
            dst[(gg * 4 + 1) * 4] = f2tf(p.y);
            dst[(gg * 4 + 2) * 4] = f2tf(p.z);
            dst[(gg * 4 + 3) * 4] = f2tf(p.w);
        }
        #pragma unroll
        for (int it = 0; it < 4; it++) {
            int qd = (tid & 3) + it * 4;
            #pragma unroll
            for (int j = 0; j < 4; j++) {
                int n = qd * 4 + j;
                int nt = n >> 3, gn = n & 7;
                VF[((vkk * 8 + nt) * 32 + gn * 4 + vt) * 2 + vword] = f2tf((&st.sv[it].x)[j]);
            }
        }
        __syncthreads();   // buf[c&1] ready; all warps past MMA(c-1)

        if (c < 15) load_stage(st, sbase, Vg, c + 1, tid);   // overlap with MMA

        const uint4* AF4 = (const uint4*)AF;
        const uint2* VF2 = (const uint2*)(AF + 8192);
        #pragma unroll
        for (int kk = 0; kk < 8; kk++) {
            uint4 a = AF4[(wid * 8 + kk) * 32 + lane];
            #pragma unroll
            for (int nt = 0; nt < 8; nt++) {
                uint2 bb = VF2[(kk * 8 + nt) * 32 + lane];
                mma_tf32(acc[nt], a.x, a.y, a.z, a.w, bb.x, bb.y);
            }
        }
        // no second sync: next iteration writes the other buffer; the single
        // sync above guarantees MMA(c-1) (last reader of that buffer) is done.
    }

    #pragma unroll
    for (int half = 0; half < 2; half++) {
        int row = qt * 128 + wid * 16 + half * 8 + g;
        float2* orow = (float2*)(out + ((size_t)bh * L + row) * D);
        #pragma unroll
        for (int nt = 0; nt < 8; nt++)
            orow[nt * 4 + t] = make_float2(acc[nt][half * 2], acc[nt][half * 2 + 1]);
    }
}

// ---------------------------------------------------------------------------
extern "C" void kernel_launch(void* const* d_in, const int* in_sizes, int n_in,
                              void* d_out, int out_size)
{
    const float* Q    = (const float*)d_in[0];
    const float* K    = (const float*)d_in[1];
    const float* V    = (const float*)d_in[2];
    const int*   mask = (const int*)  d_in[3];
    const float* bias = (const float*)d_in[4];

    float* out   = (float*)d_out;
    float* score = out + OUT_ELEMS;   // tuple order: (out, score)

    const int qk_smem = (2 * 128 * SQ + 256) * 4;        // 70656 B
    const int pv_smem = (2 * PVBUF + 128) * 4;           // 98816 B
    cudaFuncSetAttribute(qks_kernel, cudaFuncAttributeMaxDynamicSharedMemorySize, qk_smem);
    cudaFuncSetAttribute(pv_kernel,  cudaFuncAttributeMaxDynamicSharedMemorySize, pv_smem);

    qks_kernel<<<dim3(8, 64), 256, qk_smem>>>(Q, K, mask, bias, score);
    pv_kernel <<<dim3(8, 64), 256, pv_smem>>>(V, score, out);
}